// round 12
// baseline (speedup 1.0000x reference)
#include <cuda_runtime.h>
#include <cuda_fp16.h>
#include <math.h>

#define EMBED 768
#define NHEAD 12
#define HDIM  64
#define BB    4
#define NN    2048
#define MTOT  (BB * NN)          // 8192
#define QKVW  (3 * EMBED)        // 2304

// Scratch (allocation-free rule: __device__ globals)
__device__ __half g_xh[(size_t)MTOT * EMBED];      // x in fp16
__device__ __half g_wqkvh[(size_t)QKVW * EMBED];   // w_qkv fp16 (Q rows pre-scaled)
__device__ __half g_wouth[(size_t)EMBED * EMBED];  // w_out fp16
__device__ __half g_qkvh[(size_t)MTOT * QKVW];     // qkv (Q pre-scaled, log2 domain)
__device__ __half g_ctxh[(size_t)MTOT * EMBED];    // attention output fp16

#define QSCALE (0.125f * 1.4426950408889634f)      // 1/sqrt(64) * log2(e)

// ---------------------------------------------------------------------------
// helpers
// ---------------------------------------------------------------------------
__device__ __forceinline__ float fexp2(float x) {
    float y;
    asm("ex2.approx.ftz.f32 %0, %1;" : "=f"(y) : "f"(x));
    return y;
}
__device__ __forceinline__ void mma_f16(float c[4],
                                        unsigned a0, unsigned a1, unsigned a2, unsigned a3,
                                        unsigned b0, unsigned b1) {
    asm volatile(
        "mma.sync.aligned.m16n8k16.row.col.f32.f16.f16.f32 "
        "{%0,%1,%2,%3}, {%4,%5,%6,%7}, {%8,%9}, {%0,%1,%2,%3};"
        : "+f"(c[0]), "+f"(c[1]), "+f"(c[2]), "+f"(c[3])
        : "r"(a0), "r"(a1), "r"(a2), "r"(a3), "r"(b0), "r"(b1));
}
__device__ __forceinline__ void ldsm4(unsigned r[4], unsigned addr) {
    asm volatile("ldmatrix.sync.aligned.m8n8.x4.shared.b16 {%0,%1,%2,%3}, [%4];"
                 : "=r"(r[0]), "=r"(r[1]), "=r"(r[2]), "=r"(r[3]) : "r"(addr));
}
__device__ __forceinline__ void ldsm4t(unsigned r[4], unsigned addr) {
    asm volatile("ldmatrix.sync.aligned.m8n8.x4.trans.shared.b16 {%0,%1,%2,%3}, [%4];"
                 : "=r"(r[0]), "=r"(r[1]), "=r"(r[2]), "=r"(r[3]) : "r"(addr));
}
__device__ __forceinline__ unsigned smem_u32(const void* p) {
    return (unsigned)__cvta_generic_to_shared(p);
}
__device__ __forceinline__ unsigned pack_h2(float lo, float hi) {
    __half2 h = __floats2half2_rn(lo, hi);
    return *reinterpret_cast<unsigned*>(&h);
}

// ---------------------------------------------------------------------------
// fp32 -> fp16 conversion (first scaleEnd elements multiplied by scale)
// ---------------------------------------------------------------------------
__global__ void conv_f2h(const float* __restrict__ src, __half* __restrict__ dst,
                         int n, int scaleEnd, float scale)
{
    int i = (blockIdx.x * blockDim.x + threadIdx.x) * 4;
    if (i >= n) return;
    float4 v = *(const float4*)(src + i);
    if (i < scaleEnd) { v.x *= scale; v.y *= scale; v.z *= scale; v.w *= scale; }
    uint2 o;
    o.x = pack_h2(v.x, v.y);
    o.y = pack_h2(v.z, v.w);
    *(uint2*)(dst + i) = o;
}

// ---------------------------------------------------------------------------
// fp16 GEMM (NT), BK=32, double-buffered, 4 warps, warp tile 64x64.
// C = A[M][K] @ B[Nn][K]^T + bias (bias cols < scaleEnd scaled by bscale).
// 128x128 CTA tile, 128 threads. One __syncthreads per k-iter.
// Smem: half rows stride 40; 2 stages * 2 mats * 128*40*2B = 40960 B.
// ---------------------------------------------------------------------------
#define GH   40
#define GHST (128 * GH)   // halves per matrix per stage

template <bool HALF_OUT>
__global__ __launch_bounds__(128, 2) void gemm_h4(
    const __half* __restrict__ A, const __half* __restrict__ B,
    const float* __restrict__ bias, void* __restrict__ Cv,
    int M, int Nn, int K, int scaleEnd, float bscale)
{
    extern __shared__ __half gh[];
    __half* Ah = gh;               // [2][128][40]
    __half* Bh = gh + 2 * GHST;    // [2][128][40]

    const int tid  = threadIdx.x;
    const int lane = tid & 31;
    const int warp = tid >> 5;
    const int gid  = lane >> 2;
    const int tig  = lane & 3;

    const int wm = (warp >> 1) * 64;   // 0 or 64
    const int wn = (warp & 1) * 64;    // 0 or 64

    const int n0 = blockIdx.x * 128;
    const int m0 = blockIdx.y * 128;

    const int lrow = tid;              // 0..127: this thread owns row lrow of A and B

    // ldmatrix lane offsets
    const int r16 = (lane & 7) + ((lane >> 3) & 1) * 8;
    const int ca  = (lane >> 4) * 8;
    const int cb  = ((lane >> 4) & 1) * 8;

    const unsigned aBase = smem_u32(Ah) + ((wm + r16) * GH + ca) * 2;
    const unsigned bBase = smem_u32(Bh) + ((wn + r16) * GH + cb) * 2;

    float acc[4][8][4];
#pragma unroll
    for (int mi = 0; mi < 4; ++mi)
#pragma unroll
        for (int ni = 0; ni < 8; ++ni)
#pragma unroll
            for (int r = 0; r < 4; ++r) acc[mi][ni][r] = 0.0f;

    const __half* Arow = A + (size_t)(m0 + lrow) * K;
    const __half* Brow = B + (size_t)(n0 + lrow) * K;
    const int nT = K / 32;

    // prologue: full 32-half rows (4 x uint4 per thread per matrix)
    {
#pragma unroll
        for (int u = 0; u < 4; ++u) {
            *(uint4*)(Ah + lrow * GH + u * 8) = *(const uint4*)(Arow + u * 8);
            *(uint4*)(Bh + lrow * GH + u * 8) = *(const uint4*)(Brow + u * 8);
        }
    }
    __syncthreads();

    for (int kt = 0; kt < nT; ++kt) {
        const int st = kt & 1;
        uint4 av[4], bv[4];
        if (kt + 1 < nT) {
            const __half* An = Arow + (kt + 1) * 32;
            const __half* Bn = Brow + (kt + 1) * 32;
#pragma unroll
            for (int u = 0; u < 4; ++u) {
                av[u] = *(const uint4*)(An + u * 8);
                bv[u] = *(const uint4*)(Bn + u * 8);
            }
        }

        const unsigned aS = aBase + st * (GHST * 2);
        const unsigned bS = bBase + st * (GHST * 2);
#pragma unroll
        for (int ks = 0; ks < 2; ++ks) {
            const unsigned koff = ks * 32;   // 16 halves
            unsigned af[4][4], bf[4][4];
#pragma unroll
            for (int mi = 0; mi < 4; ++mi)
                ldsm4(af[mi], aS + mi * (16 * GH * 2) + koff);
#pragma unroll
            for (int ng = 0; ng < 4; ++ng)
                ldsm4(bf[ng], bS + ng * (16 * GH * 2) + koff);
#pragma unroll
            for (int mi = 0; mi < 4; ++mi)
#pragma unroll
                for (int ni = 0; ni < 8; ++ni)
                    mma_f16(acc[mi][ni], af[mi][0], af[mi][1], af[mi][2], af[mi][3],
                            bf[ni >> 1][ni & 1], bf[ni >> 1][(ni & 1) + 2]);
        }

        if (kt + 1 < nT) {
            __half* Ad = Ah + (st ^ 1) * GHST;
            __half* Bd = Bh + (st ^ 1) * GHST;
#pragma unroll
            for (int u = 0; u < 4; ++u) {
                *(uint4*)(Ad + lrow * GH + u * 8) = av[u];
                *(uint4*)(Bd + lrow * GH + u * 8) = bv[u];
            }
            __syncthreads();
        }
    }

    // Epilogue: bias (+optional scale) then store fp16 or fp32
#pragma unroll
    for (int ni = 0; ni < 8; ++ni) {
        const int col = n0 + wn + ni * 8 + 2 * tig;
        const float bs = (col < scaleEnd) ? bscale : 1.0f;
        const float bx = bias[col] * bs;
        const float by = bias[col + 1] * bs;
#pragma unroll
        for (int mi = 0; mi < 4; ++mi) {
            const int row = m0 + wm + mi * 16 + gid;
            if (HALF_OUT) {
                __half* C = (__half*)Cv;
                *(unsigned*)(C + (size_t)row * Nn + col) =
                    pack_h2(acc[mi][ni][0] + bx, acc[mi][ni][1] + by);
                *(unsigned*)(C + (size_t)(row + 8) * Nn + col) =
                    pack_h2(acc[mi][ni][2] + bx, acc[mi][ni][3] + by);
            } else {
                float* C = (float*)Cv;
                *(float2*)(C + (size_t)row * Nn + col) =
                    make_float2(acc[mi][ni][0] + bx, acc[mi][ni][1] + by);
                *(float2*)(C + (size_t)(row + 8) * Nn + col) =
                    make_float2(acc[mi][ni][2] + bx, acc[mi][ni][3] + by);
            }
        }
    }
}

// ---------------------------------------------------------------------------
// Flash attention: all-fp16 mma (fp32 accum), fp16 gmem I/O, double-buffered
// K/V tiles with ONE barrier per iteration.
// Smem halves: Q[128][72] | K0[64][72] | V0[64][72] | K1[64][72] | V1[64][72]
// total = 384*72*2 = 55296 B (2 CTAs/SM).
// ---------------------------------------------------------------------------
#define AH_Q  0
#define AH_K0 (128 * 72)
#define AH_V0 (192 * 72)
#define AH_K1 (256 * 72)
#define AH_V1 (320 * 72)
#define KVBUF (128 * 72)          // halves between buf0 and buf1 (K0->K1)
#define ATT_BYTES (384 * 72 * 2)  // 55296

__global__ __launch_bounds__(256, 2) void attn_flash_f16()
{
    extern __shared__ __half ah[];
    __half* qh = ah + AH_Q;

    const int tid  = threadIdx.x;
    const int lane = tid & 31;
    const int warp = tid >> 5;
    const int gid  = lane >> 2;
    const int tig  = lane & 3;
    const int wm   = warp * 16;

    const int b  = blockIdx.y / NHEAD;
    const int h  = blockIdx.y % NHEAD;
    const int q0 = blockIdx.x * 128;

    // ldmatrix lane offsets
    const int r16 = (lane & 7) + ((lane >> 3) & 1) * 8;
    const int caQ = (lane >> 4) * 8;
    const int cbKV = ((lane >> 4) & 1) * 8;

    const unsigned qA  = smem_u32(qh) + ((wm + r16) * 72 + caQ) * 2;
    const unsigned kB0 = smem_u32(ah + AH_K0) + (r16 * 72 + cbKV) * 2;
    const unsigned vB0 = smem_u32(ah + AH_V0) + (r16 * 72 + cbKV) * 2;

    // ---- load Q tile (already scaled, fp16 in gmem -> pure copy) ----
    {
        const int qrow = tid & 127;
        const int qdh  = (tid >> 7) * 32;
        const __half* src = g_qkvh + (size_t)(b * NN + q0 + qrow) * QKVW + h * HDIM + qdh;
        __half* dst = qh + qrow * 72 + qdh;
        *(uint4*)(dst)      = *(const uint4*)(src);
        *(uint4*)(dst + 8)  = *(const uint4*)(src + 8);
        *(uint4*)(dst + 16) = *(const uint4*)(src + 16);
        *(uint4*)(dst + 24) = *(const uint4*)(src + 24);
    }

    // K/V loader: kr = row, sel 0,1 = K d-halves; 2,3 = V d-halves
    const int kr   = tid & 63;
    const int sel  = tid >> 6;
    const int kdh  = (sel & 1) * 32;
    const size_t kvoff = (size_t)h * HDIM + kdh + ((sel >> 1) ? 2 * EMBED : EMBED);
    __half* kvdst0 = ah + ((sel >> 1) ? AH_V0 : AH_K0) + kr * 72 + kdh;

    uint4 pf[4];
    // prologue: tile 0 -> buf0, prefetch tile 1 -> regs
    {
        const __half* srcp = g_qkvh + (size_t)(b * NN + kr) * QKVW + kvoff;
#pragma unroll
        for (int u = 0; u < 4; ++u) pf[u] = *(const uint4*)(srcp + u * 8);
#pragma unroll
        for (int u = 0; u < 4; ++u) *(uint4*)(kvdst0 + u * 8) = pf[u];
        const __half* srcn = g_qkvh + (size_t)(b * NN + 64 + kr) * QKVW + kvoff;
#pragma unroll
        for (int u = 0; u < 4; ++u) pf[u] = *(const uint4*)(srcn + u * 8);
    }
    __syncthreads();

    float m0r = -1.0e30f, m1r = -1.0e30f;
    float l0 = 0.0f, l1 = 0.0f;
    float O[8][4];
#pragma unroll
    for (int ni = 0; ni < 8; ++ni)
#pragma unroll
        for (int r = 0; r < 4; ++r) O[ni][r] = 0.0f;

    const int NT = NN / 64;
    for (int kt = 0; kt < NT; ++kt) {
        const int buf = kt & 1;
        const unsigned kB = kB0 + buf * (KVBUF * 2);
        const unsigned vB = vB0 + buf * (KVBUF * 2);

        // ---- S = Qhat @ K^T (fp16 mma) ----
        float s[8][4];
#pragma unroll
        for (int ni = 0; ni < 8; ++ni)
#pragma unroll
            for (int r = 0; r < 4; ++r) s[ni][r] = 0.0f;
#pragma unroll
        for (int ks = 0; ks < 4; ++ks) {          // d in 16-chunks
            unsigned aq[4];
            ldsm4(aq, qA + ks * 32);
#pragma unroll
            for (int j = 0; j < 4; ++j) {         // key 16-groups
                unsigned bk[4];
                ldsm4(bk, kB + j * (16 * 72 * 2) + ks * 32);
                mma_f16(s[2 * j],     aq[0], aq[1], aq[2], aq[3], bk[0], bk[2]);
                mma_f16(s[2 * j + 1], aq[0], aq[1], aq[2], aq[3], bk[1], bk[3]);
            }
        }

        // ---- online softmax (log2 domain) ----
        float rm0 = -1.0e30f, rm1 = -1.0e30f;
#pragma unroll
        for (int ni = 0; ni < 8; ++ni) {
            rm0 = fmaxf(rm0, fmaxf(s[ni][0], s[ni][1]));
            rm1 = fmaxf(rm1, fmaxf(s[ni][2], s[ni][3]));
        }
        rm0 = fmaxf(rm0, __shfl_xor_sync(0xffffffffu, rm0, 1));
        rm0 = fmaxf(rm0, __shfl_xor_sync(0xffffffffu, rm0, 2));
        rm1 = fmaxf(rm1, __shfl_xor_sync(0xffffffffu, rm1, 1));
        rm1 = fmaxf(rm1, __shfl_xor_sync(0xffffffffu, rm1, 2));

        const float mn0 = fmaxf(m0r, rm0);
        const float mn1 = fmaxf(m1r, rm1);
        const float al0 = fexp2(m0r - mn0);
        const float al1 = fexp2(m1r - mn1);
        m0r = mn0; m1r = mn1;

        float ps0 = 0.0f, ps1 = 0.0f;
#pragma unroll
        for (int ni = 0; ni < 8; ++ni) {
            s[ni][0] = fexp2(s[ni][0] - mn0);
            s[ni][1] = fexp2(s[ni][1] - mn0);
            s[ni][2] = fexp2(s[ni][2] - mn1);
            s[ni][3] = fexp2(s[ni][3] - mn1);
            ps0 += s[ni][0] + s[ni][1];
            ps1 += s[ni][2] + s[ni][3];
        }
        ps0 += __shfl_xor_sync(0xffffffffu, ps0, 1);
        ps0 += __shfl_xor_sync(0xffffffffu, ps0, 2);
        ps1 += __shfl_xor_sync(0xffffffffu, ps1, 1);
        ps1 += __shfl_xor_sync(0xffffffffu, ps1, 2);
        l0 = l0 * al0 + ps0;
        l1 = l1 * al1 + ps1;

#pragma unroll
        for (int ni = 0; ni < 8; ++ni) {
            O[ni][0] *= al0; O[ni][1] *= al0;
            O[ni][2] *= al1; O[ni][3] *= al1;
        }

        // ---- O += P @ V : P in registers, V via ldmatrix.trans ----
#pragma unroll
        for (int j = 0; j < 4; ++j) {             // key 16-groups (k dim)
            const unsigned a0 = pack_h2(s[2 * j][0],     s[2 * j][1]);
            const unsigned a1 = pack_h2(s[2 * j][2],     s[2 * j][3]);
            const unsigned a2 = pack_h2(s[2 * j + 1][0], s[2 * j + 1][1]);
            const unsigned a3 = pack_h2(s[2 * j + 1][2], s[2 * j + 1][3]);
#pragma unroll
            for (int p = 0; p < 4; ++p) {         // d 16-groups (n dim)
                unsigned bv[4];
                ldsm4t(bv, vB + j * (16 * 72 * 2) + p * 32);
                mma_f16(O[2 * p],     a0, a1, a2, a3, bv[0], bv[1]);
                mma_f16(O[2 * p + 1], a0, a1, a2, a3, bv[2], bv[3]);
            }
        }

        // ---- rotate: store prefetched tile into OTHER buffer, prefetch next ----
        if (kt + 1 < NT) {
            __half* dst = kvdst0 + (buf ^ 1) * KVBUF;
#pragma unroll
            for (int u = 0; u < 4; ++u) *(uint4*)(dst + u * 8) = pf[u];
            if (kt + 2 < NT) {
                const __half* srcn = g_qkvh + (size_t)(b * NN + (kt + 2) * 64 + kr) * QKVW + kvoff;
#pragma unroll
                for (int u = 0; u < 4; ++u) pf[u] = *(const uint4*)(srcn + u * 8);
            }
            __syncthreads();
        }
    }

    // ---- normalize and write ctx (fp16) ----
    const float inv0 = 1.0f / l0;
    const float inv1 = 1.0f / l1;
    __half* dst0 = g_ctxh + (size_t)(b * NN + q0 + wm + gid) * EMBED + h * HDIM;
    __half* dst1 = g_ctxh + (size_t)(b * NN + q0 + wm + gid + 8) * EMBED + h * HDIM;
#pragma unroll
    for (int ni = 0; ni < 8; ++ni) {
        const int col = ni * 8 + 2 * tig;
        *(unsigned*)(dst0 + col) = pack_h2(O[ni][0] * inv0, O[ni][1] * inv0);
        *(unsigned*)(dst1 + col) = pack_h2(O[ni][2] * inv1, O[ni][3] * inv1);
    }
}

// ---------------------------------------------------------------------------
extern "C" void kernel_launch(void* const* d_in, const int* in_sizes, int n_in,
                              void* d_out, int out_size)
{
    (void)in_sizes; (void)n_in; (void)out_size;
    const float* x     = (const float*)d_in[0];
    const float* w_qkv = (const float*)d_in[1];
    const float* b_qkv = (const float*)d_in[2];
    const float* w_out = (const float*)d_in[3];
    const float* b_out = (const float*)d_in[4];
    float* out = (float*)d_out;

    __half *xh, *wqkvh, *wouth, *qkvh, *ctxh;
    cudaGetSymbolAddress((void**)&xh,    g_xh);
    cudaGetSymbolAddress((void**)&wqkvh, g_wqkvh);
    cudaGetSymbolAddress((void**)&wouth, g_wouth);
    cudaGetSymbolAddress((void**)&qkvh,  g_qkvh);
    cudaGetSymbolAddress((void**)&ctxh,  g_ctxh);

    const int gemm_smem = 4 * GHST * 2;   // 40960
    const int attn_smem = ATT_BYTES;      // 55296

    static int attrs_set = 0;
    if (!attrs_set) {
        cudaFuncSetAttribute(gemm_h4<true>,
                             cudaFuncAttributeMaxDynamicSharedMemorySize, gemm_smem);
        cudaFuncSetAttribute(gemm_h4<false>,
                             cudaFuncAttributeMaxDynamicSharedMemorySize, gemm_smem);
        cudaFuncSetAttribute(attn_flash_f16,
                             cudaFuncAttributeMaxDynamicSharedMemorySize, attn_smem);
        attrs_set = 1;
    }

    // 0) fp32 -> fp16 conversions (Q rows of w_qkv pre-scaled by QSCALE)
    {
        const int n1 = MTOT * EMBED;
        conv_f2h<<<n1 / 4 / 256, 256>>>(x, xh, n1, 0, 1.0f);
        const int n2 = QKVW * EMBED;
        conv_f2h<<<n2 / 4 / 256, 256>>>(w_qkv, wqkvh, n2, EMBED * EMBED, QSCALE);
        const int n3 = EMBED * EMBED;
        conv_f2h<<<n3 / 4 / 256, 256>>>(w_out, wouth, n3, 0, 1.0f);
    }

    // 1) QKV projection (half in, half out; Q bias scaled in epilogue)
    {
        dim3 grid(QKVW / 128, MTOT / 128);
        gemm_h4<true><<<grid, 128, gemm_smem>>>(xh, wqkvh, b_qkv, qkvh,
                                                MTOT, QKVW, EMBED, EMBED, QSCALE);
    }

    // 2) Flash attention (all fp16 I/O, double-buffered K/V)
    {
        dim3 grid(NN / 128, BB * NHEAD);
        attn_flash_f16<<<grid, 256, attn_smem>>>();
    }

    // 3) Output projection (half in, fp32 out + bias)
    {
        dim3 grid(EMBED / 128, MTOT / 128);
        gemm_h4<false><<<grid, 128, gemm_smem>>>(ctxh, wouth, b_out, out,
                                                 MTOT, EMBED, EMBED, 0, 1.0f);
    }
}

// round 13
// speedup vs baseline: 1.0915x; 1.0915x over previous
#include <cuda_runtime.h>
#include <cuda_fp16.h>
#include <math.h>

#define EMBED 768
#define NHEAD 12
#define HDIM  64
#define BB    4
#define NN    2048
#define MTOT  (BB * NN)          // 8192
#define QKVW  (3 * EMBED)        // 2304

// Scratch (allocation-free rule: __device__ globals)
__device__ __half g_xh[(size_t)MTOT * EMBED];      // x in fp16
__device__ __half g_wqkvh[(size_t)QKVW * EMBED];   // w_qkv fp16 (Q rows pre-scaled)
__device__ __half g_wouth[(size_t)EMBED * EMBED];  // w_out fp16
__device__ __half g_qkvh[(size_t)MTOT * QKVW];     // qkv (Q pre-scaled, log2 domain)
__device__ __half g_ctxh[(size_t)MTOT * EMBED];    // attention output fp16

#define QSCALE (0.125f * 1.4426950408889634f)      // 1/sqrt(64) * log2(e)

// ---------------------------------------------------------------------------
// helpers
// ---------------------------------------------------------------------------
__device__ __forceinline__ float fexp2(float x) {
    float y;
    asm("ex2.approx.ftz.f32 %0, %1;" : "=f"(y) : "f"(x));
    return y;
}
__device__ __forceinline__ void mma_f16(float c[4],
                                        unsigned a0, unsigned a1, unsigned a2, unsigned a3,
                                        unsigned b0, unsigned b1) {
    asm volatile(
        "mma.sync.aligned.m16n8k16.row.col.f32.f16.f16.f32 "
        "{%0,%1,%2,%3}, {%4,%5,%6,%7}, {%8,%9}, {%0,%1,%2,%3};"
        : "+f"(c[0]), "+f"(c[1]), "+f"(c[2]), "+f"(c[3])
        : "r"(a0), "r"(a1), "r"(a2), "r"(a3), "r"(b0), "r"(b1));
}
__device__ __forceinline__ void ldsm4(unsigned r[4], unsigned addr) {
    asm volatile("ldmatrix.sync.aligned.m8n8.x4.shared.b16 {%0,%1,%2,%3}, [%4];"
                 : "=r"(r[0]), "=r"(r[1]), "=r"(r[2]), "=r"(r[3]) : "r"(addr));
}
__device__ __forceinline__ void ldsm4t(unsigned r[4], unsigned addr) {
    asm volatile("ldmatrix.sync.aligned.m8n8.x4.trans.shared.b16 {%0,%1,%2,%3}, [%4];"
                 : "=r"(r[0]), "=r"(r[1]), "=r"(r[2]), "=r"(r[3]) : "r"(addr));
}
__device__ __forceinline__ unsigned smem_u32(const void* p) {
    return (unsigned)__cvta_generic_to_shared(p);
}
__device__ __forceinline__ unsigned pack_h2(float lo, float hi) {
    __half2 h = __floats2half2_rn(lo, hi);
    return *reinterpret_cast<unsigned*>(&h);
}
__device__ __forceinline__ void cpa16(unsigned s, const void* g) {
    asm volatile("cp.async.cg.shared.global [%0], [%1], 16;" :: "r"(s), "l"(g) : "memory");
}
#define CP_COMMIT() asm volatile("cp.async.commit_group;" ::: "memory")
#define CP_WAIT0()  asm volatile("cp.async.wait_group 0;" ::: "memory")

// ---------------------------------------------------------------------------
// fp32 -> fp16 conversion (first scaleEnd elements multiplied by scale)
// ---------------------------------------------------------------------------
__global__ void conv_f2h(const float* __restrict__ src, __half* __restrict__ dst,
                         int n, int scaleEnd, float scale)
{
    int i = (blockIdx.x * blockDim.x + threadIdx.x) * 4;
    if (i >= n) return;
    float4 v = *(const float4*)(src + i);
    if (i < scaleEnd) { v.x *= scale; v.y *= scale; v.z *= scale; v.w *= scale; }
    uint2 o;
    o.x = pack_h2(v.x, v.y);
    o.y = pack_h2(v.z, v.w);
    *(uint2*)(dst + i) = o;
}

// ---------------------------------------------------------------------------
// fp16 GEMM (NT), BK=32, double-buffered via cp.async, 8 warps, warp 64x32.
// C = A[M][K] @ B[Nn][K]^T + bias (bias cols < scaleEnd scaled by bscale).
// Smem: half rows stride 40; 2 stages * 2 mats * 128*40*2B = 40960 B.
// ---------------------------------------------------------------------------
#define GH   40
#define GHST (128 * GH)   // halves per matrix per stage

template <bool HALF_OUT>
__global__ __launch_bounds__(256, 2) void gemm_h_db(
    const __half* __restrict__ A, const __half* __restrict__ B,
    const float* __restrict__ bias, void* __restrict__ Cv,
    int M, int Nn, int K, int scaleEnd, float bscale)
{
    extern __shared__ __half gh[];
    __half* Ah = gh;               // [2][128][40]
    __half* Bh = gh + 2 * GHST;    // [2][128][40]

    const int tid  = threadIdx.x;
    const int lane = tid & 31;
    const int warp = tid >> 5;
    const int gid  = lane >> 2;
    const int tig  = lane & 3;

    const int wm = (warp >> 2) * 64;   // 0 or 64
    const int wn = (warp & 3) * 32;    // 0,32,64,96

    const int n0 = blockIdx.x * 128;
    const int m0 = blockIdx.y * 128;

    const int lrow = tid >> 1;         // 0..127
    const int lk   = (tid & 1) * 16;   // 0 or 16 (halves)

    // ldmatrix lane offsets
    const int r16 = (lane & 7) + ((lane >> 3) & 1) * 8;
    const int ca  = (lane >> 4) * 8;
    const int cb  = ((lane >> 4) & 1) * 8;

    const unsigned aBase = smem_u32(Ah) + ((wm + r16) * GH + ca) * 2;
    const unsigned bBase = smem_u32(Bh) + ((wn + r16) * GH + cb) * 2;

    // cp.async destination addresses (this thread's slots)
    const unsigned aDst = smem_u32(Ah + lrow * GH + lk);
    const unsigned bDst = smem_u32(Bh + lrow * GH + lk);

    float acc[4][4][4];
#pragma unroll
    for (int mi = 0; mi < 4; ++mi)
#pragma unroll
        for (int ni = 0; ni < 4; ++ni)
#pragma unroll
            for (int r = 0; r < 4; ++r) acc[mi][ni][r] = 0.0f;

    const __half* Arow = A + (size_t)(m0 + lrow) * K + lk;
    const __half* Brow = B + (size_t)(n0 + lrow) * K + lk;
    const int nT = K / 32;

    // prologue: stage 0 via cp.async
    cpa16(aDst,      Arow);
    cpa16(aDst + 16, Arow + 8);
    cpa16(bDst,      Brow);
    cpa16(bDst + 16, Brow + 8);
    CP_COMMIT();
    CP_WAIT0();
    __syncthreads();

    for (int kt = 0; kt < nT; ++kt) {
        const int st = kt & 1;
        // issue next stage's loads (overlap with MMAs below)
        if (kt + 1 < nT) {
            const unsigned soff = (st ^ 1) * (GHST * 2);
            const __half* An = Arow + (kt + 1) * 32;
            const __half* Bn = Brow + (kt + 1) * 32;
            cpa16(aDst + soff,      An);
            cpa16(aDst + soff + 16, An + 8);
            cpa16(bDst + soff,      Bn);
            cpa16(bDst + soff + 16, Bn + 8);
            CP_COMMIT();
        }

        const unsigned aS = aBase + st * (GHST * 2);
        const unsigned bS = bBase + st * (GHST * 2);
#pragma unroll
        for (int ks = 0; ks < 2; ++ks) {
            const unsigned koff = ks * 32;   // 16 halves
            unsigned af[4][4], bf[2][4];
#pragma unroll
            for (int mi = 0; mi < 4; ++mi)
                ldsm4(af[mi], aS + mi * (16 * GH * 2) + koff);
#pragma unroll
            for (int ng = 0; ng < 2; ++ng)
                ldsm4(bf[ng], bS + ng * (16 * GH * 2) + koff);
#pragma unroll
            for (int mi = 0; mi < 4; ++mi)
#pragma unroll
                for (int ni = 0; ni < 4; ++ni)
                    mma_f16(acc[mi][ni], af[mi][0], af[mi][1], af[mi][2], af[mi][3],
                            bf[ni >> 1][ni & 1], bf[ni >> 1][(ni & 1) + 2]);
        }

        if (kt + 1 < nT) {
            CP_WAIT0();
            __syncthreads();
        }
    }

    // Epilogue: bias (+optional scale) then store fp16 or fp32
#pragma unroll
    for (int ni = 0; ni < 4; ++ni) {
        const int col = n0 + wn + ni * 8 + 2 * tig;
        const float bs = (col < scaleEnd) ? bscale : 1.0f;
        const float bx = bias[col] * bs;
        const float by = bias[col + 1] * bs;
#pragma unroll
        for (int mi = 0; mi < 4; ++mi) {
            const int row = m0 + wm + mi * 16 + gid;
            if (HALF_OUT) {
                __half* C = (__half*)Cv;
                *(unsigned*)(C + (size_t)row * Nn + col) =
                    pack_h2(acc[mi][ni][0] + bx, acc[mi][ni][1] + by);
                *(unsigned*)(C + (size_t)(row + 8) * Nn + col) =
                    pack_h2(acc[mi][ni][2] + bx, acc[mi][ni][3] + by);
            } else {
                float* C = (float*)Cv;
                *(float2*)(C + (size_t)row * Nn + col) =
                    make_float2(acc[mi][ni][0] + bx, acc[mi][ni][1] + by);
                *(float2*)(C + (size_t)(row + 8) * Nn + col) =
                    make_float2(acc[mi][ni][2] + bx, acc[mi][ni][3] + by);
            }
        }
    }
}

// ---------------------------------------------------------------------------
// Flash attention: all-fp16 mma (fp32 accum), fp16 gmem I/O, double-buffered
// K/V via cp.async, ONE barrier per iteration.
// Smem halves: Q[128][72] | K0[64][72] | V0[64][72] | K1[64][72] | V1[64][72]
// total = 384*72*2 = 55296 B (2 CTAs/SM).
// ---------------------------------------------------------------------------
#define AH_Q  0
#define AH_K0 (128 * 72)
#define AH_V0 (192 * 72)
#define KVBUF (128 * 72)          // halves between buf0 and buf1
#define ATT_BYTES (384 * 72 * 2)  // 55296

__global__ __launch_bounds__(256, 2) void attn_flash_f16()
{
    extern __shared__ __half ah[];
    __half* qh = ah + AH_Q;

    const int tid  = threadIdx.x;
    const int lane = tid & 31;
    const int warp = tid >> 5;
    const int gid  = lane >> 2;
    const int tig  = lane & 3;
    const int wm   = warp * 16;

    const int b  = blockIdx.y / NHEAD;
    const int h  = blockIdx.y % NHEAD;
    const int q0 = blockIdx.x * 128;

    // ldmatrix lane offsets
    const int r16 = (lane & 7) + ((lane >> 3) & 1) * 8;
    const int caQ = (lane >> 4) * 8;
    const int cbKV = ((lane >> 4) & 1) * 8;

    const unsigned qA  = smem_u32(qh) + ((wm + r16) * 72 + caQ) * 2;
    const unsigned kB0 = smem_u32(ah + AH_K0) + (r16 * 72 + cbKV) * 2;
    const unsigned vB0 = smem_u32(ah + AH_V0) + (r16 * 72 + cbKV) * 2;

    // ---- load Q tile (pure copy) ----
    {
        const int qrow = tid & 127;
        const int qdh  = (tid >> 7) * 32;
        const __half* src = g_qkvh + (size_t)(b * NN + q0 + qrow) * QKVW + h * HDIM + qdh;
        __half* dst = qh + qrow * 72 + qdh;
        *(uint4*)(dst)      = *(const uint4*)(src);
        *(uint4*)(dst + 8)  = *(const uint4*)(src + 8);
        *(uint4*)(dst + 16) = *(const uint4*)(src + 16);
        *(uint4*)(dst + 24) = *(const uint4*)(src + 24);
    }

    // K/V loader: kr = row, sel 0,1 = K d-halves; 2,3 = V d-halves
    const int kr   = tid & 63;
    const int sel  = tid >> 6;
    const int kdh  = (sel & 1) * 32;
    const size_t kvoff = (size_t)h * HDIM + kdh + ((sel >> 1) ? 2 * EMBED : EMBED);
    const unsigned kvDst0 = smem_u32(ah + ((sel >> 1) ? AH_V0 : AH_K0) + kr * 72 + kdh);
    const __half* kvSrc = g_qkvh + (size_t)(b * NN + kr) * QKVW + kvoff;

    // prologue: tile 0 -> buf0 via cp.async
    {
#pragma unroll
        for (int u = 0; u < 4; ++u)
            cpa16(kvDst0 + u * 16, kvSrc + u * 8);
        CP_COMMIT();
        CP_WAIT0();
    }
    __syncthreads();

    float m0r = -1.0e30f, m1r = -1.0e30f;
    float l0 = 0.0f, l1 = 0.0f;
    float O[8][4];
#pragma unroll
    for (int ni = 0; ni < 8; ++ni)
#pragma unroll
        for (int r = 0; r < 4; ++r) O[ni][r] = 0.0f;

    const int NT = NN / 64;
    for (int kt = 0; kt < NT; ++kt) {
        const int buf = kt & 1;
        // issue next K/V tile into the other buffer (overlaps with compute)
        if (kt + 1 < NT) {
            const unsigned d = kvDst0 + ((buf ^ 1) * KVBUF) * 2;
            const __half* s2 = kvSrc + (size_t)(kt + 1) * 64 * QKVW;
#pragma unroll
            for (int u = 0; u < 4; ++u)
                cpa16(d + u * 16, s2 + u * 8);
            CP_COMMIT();
        }

        const unsigned kB = kB0 + buf * (KVBUF * 2);
        const unsigned vB = vB0 + buf * (KVBUF * 2);

        // ---- S = Qhat @ K^T (fp16 mma) ----
        float s[8][4];
#pragma unroll
        for (int ni = 0; ni < 8; ++ni)
#pragma unroll
            for (int r = 0; r < 4; ++r) s[ni][r] = 0.0f;
#pragma unroll
        for (int ks = 0; ks < 4; ++ks) {          // d in 16-chunks
            unsigned aq[4];
            ldsm4(aq, qA + ks * 32);
#pragma unroll
            for (int j = 0; j < 4; ++j) {         // key 16-groups
                unsigned bk[4];
                ldsm4(bk, kB + j * (16 * 72 * 2) + ks * 32);
                mma_f16(s[2 * j],     aq[0], aq[1], aq[2], aq[3], bk[0], bk[2]);
                mma_f16(s[2 * j + 1], aq[0], aq[1], aq[2], aq[3], bk[1], bk[3]);
            }
        }

        // ---- online softmax (log2 domain) ----
        float rm0 = -1.0e30f, rm1 = -1.0e30f;
#pragma unroll
        for (int ni = 0; ni < 8; ++ni) {
            rm0 = fmaxf(rm0, fmaxf(s[ni][0], s[ni][1]));
            rm1 = fmaxf(rm1, fmaxf(s[ni][2], s[ni][3]));
        }
        rm0 = fmaxf(rm0, __shfl_xor_sync(0xffffffffu, rm0, 1));
        rm0 = fmaxf(rm0, __shfl_xor_sync(0xffffffffu, rm0, 2));
        rm1 = fmaxf(rm1, __shfl_xor_sync(0xffffffffu, rm1, 1));
        rm1 = fmaxf(rm1, __shfl_xor_sync(0xffffffffu, rm1, 2));

        const float mn0 = fmaxf(m0r, rm0);
        const float mn1 = fmaxf(m1r, rm1);
        const float al0 = fexp2(m0r - mn0);
        const float al1 = fexp2(m1r - mn1);
        m0r = mn0; m1r = mn1;

        float ps0 = 0.0f, ps1 = 0.0f;
#pragma unroll
        for (int ni = 0; ni < 8; ++ni) {
            s[ni][0] = fexp2(s[ni][0] - mn0);
            s[ni][1] = fexp2(s[ni][1] - mn0);
            s[ni][2] = fexp2(s[ni][2] - mn1);
            s[ni][3] = fexp2(s[ni][3] - mn1);
            ps0 += s[ni][0] + s[ni][1];
            ps1 += s[ni][2] + s[ni][3];
        }
        ps0 += __shfl_xor_sync(0xffffffffu, ps0, 1);
        ps0 += __shfl_xor_sync(0xffffffffu, ps0, 2);
        ps1 += __shfl_xor_sync(0xffffffffu, ps1, 1);
        ps1 += __shfl_xor_sync(0xffffffffu, ps1, 2);
        l0 = l0 * al0 + ps0;
        l1 = l1 * al1 + ps1;

#pragma unroll
        for (int ni = 0; ni < 8; ++ni) {
            O[ni][0] *= al0; O[ni][1] *= al0;
            O[ni][2] *= al1; O[ni][3] *= al1;
        }

        // ---- O += P @ V : P in registers, V via ldmatrix.trans ----
#pragma unroll
        for (int j = 0; j < 4; ++j) {             // key 16-groups (k dim)
            const unsigned a0 = pack_h2(s[2 * j][0],     s[2 * j][1]);
            const unsigned a1 = pack_h2(s[2 * j][2],     s[2 * j][3]);
            const unsigned a2 = pack_h2(s[2 * j + 1][0], s[2 * j + 1][1]);
            const unsigned a3 = pack_h2(s[2 * j + 1][2], s[2 * j + 1][3]);
#pragma unroll
            for (int p = 0; p < 4; ++p) {         // d 16-groups (n dim)
                unsigned bv[4];
                ldsm4t(bv, vB + j * (16 * 72 * 2) + p * 32);
                mma_f16(O[2 * p],     a0, a1, a2, a3, bv[0], bv[1]);
                mma_f16(O[2 * p + 1], a0, a1, a2, a3, bv[2], bv[3]);
            }
        }

        if (kt + 1 < NT) {
            CP_WAIT0();
            __syncthreads();
        }
    }

    // ---- normalize and write ctx (fp16) ----
    const float inv0 = 1.0f / l0;
    const float inv1 = 1.0f / l1;
    __half* dst0 = g_ctxh + (size_t)(b * NN + q0 + wm + gid) * EMBED + h * HDIM;
    __half* dst1 = g_ctxh + (size_t)(b * NN + q0 + wm + gid + 8) * EMBED + h * HDIM;
#pragma unroll
    for (int ni = 0; ni < 8; ++ni) {
        const int col = ni * 8 + 2 * tig;
        *(unsigned*)(dst0 + col) = pack_h2(O[ni][0] * inv0, O[ni][1] * inv0);
        *(unsigned*)(dst1 + col) = pack_h2(O[ni][2] * inv1, O[ni][3] * inv1);
    }
}

// ---------------------------------------------------------------------------
extern "C" void kernel_launch(void* const* d_in, const int* in_sizes, int n_in,
                              void* d_out, int out_size)
{
    (void)in_sizes; (void)n_in; (void)out_size;
    const float* x     = (const float*)d_in[0];
    const float* w_qkv = (const float*)d_in[1];
    const float* b_qkv = (const float*)d_in[2];
    const float* w_out = (const float*)d_in[3];
    const float* b_out = (const float*)d_in[4];
    float* out = (float*)d_out;

    __half *xh, *wqkvh, *wouth, *qkvh, *ctxh;
    cudaGetSymbolAddress((void**)&xh,    g_xh);
    cudaGetSymbolAddress((void**)&wqkvh, g_wqkvh);
    cudaGetSymbolAddress((void**)&wouth, g_wouth);
    cudaGetSymbolAddress((void**)&qkvh,  g_qkvh);
    cudaGetSymbolAddress((void**)&ctxh,  g_ctxh);

    const int gemm_smem = 4 * GHST * 2;   // 40960
    const int attn_smem = ATT_BYTES;      // 55296

    static int attrs_set = 0;
    if (!attrs_set) {
        cudaFuncSetAttribute(gemm_h_db<true>,
                             cudaFuncAttributeMaxDynamicSharedMemorySize, gemm_smem);
        cudaFuncSetAttribute(gemm_h_db<false>,
                             cudaFuncAttributeMaxDynamicSharedMemorySize, gemm_smem);
        cudaFuncSetAttribute(attn_flash_f16,
                             cudaFuncAttributeMaxDynamicSharedMemorySize, attn_smem);
        attrs_set = 1;
    }

    // 0) fp32 -> fp16 conversions (Q rows of w_qkv pre-scaled by QSCALE)
    {
        const int n1 = MTOT * EMBED;
        conv_f2h<<<n1 / 4 / 256, 256>>>(x, xh, n1, 0, 1.0f);
        const int n2 = QKVW * EMBED;
        conv_f2h<<<n2 / 4 / 256, 256>>>(w_qkv, wqkvh, n2, EMBED * EMBED, QSCALE);
        const int n3 = EMBED * EMBED;
        conv_f2h<<<n3 / 4 / 256, 256>>>(w_out, wouth, n3, 0, 1.0f);
    }

    // 1) QKV projection (half in, half out; Q bias scaled in epilogue)
    {
        dim3 grid(QKVW / 128, MTOT / 128);
        gemm_h_db<true><<<grid, 256, gemm_smem>>>(xh, wqkvh, b_qkv, qkvh,
                                                  MTOT, QKVW, EMBED, EMBED, QSCALE);
    }

    // 2) Flash attention (all fp16 I/O, cp.async double-buffered K/V)
    {
        dim3 grid(NN / 128, BB * NHEAD);
        attn_flash_f16<<<grid, 256, attn_smem>>>();
    }

    // 3) Output projection (half in, fp32 out + bias)
    {
        dim3 grid(EMBED / 128, MTOT / 128);
        gemm_h_db<false><<<grid, 256, gemm_smem>>>(ctxh, wouth, b_out, out,
                                                   MTOT, EMBED, EMBED, 0, 1.0f);
    }
}

// round 14
// speedup vs baseline: 1.1527x; 1.0560x over previous
#include <cuda_runtime.h>
#include <cuda_fp16.h>
#include <math.h>

#define EMBED 768
#define NHEAD 12
#define HDIM  64
#define BB    4
#define NN    2048
#define MTOT  (BB * NN)          // 8192
#define QKVW  (3 * EMBED)        // 2304

// Scratch (allocation-free rule: __device__ globals)
__device__ __half g_xh[(size_t)MTOT * EMBED];      // x in fp16
__device__ __half g_wqkvh[(size_t)QKVW * EMBED];   // w_qkv fp16 (Q rows pre-scaled)
__device__ __half g_wouth[(size_t)EMBED * EMBED];  // w_out fp16
__device__ __half g_qkvh[(size_t)MTOT * QKVW];     // qkv (Q pre-scaled, log2 domain)
__device__ __half g_ctxh[(size_t)MTOT * EMBED];    // attention output fp16

#define QSCALE (0.125f * 1.4426950408889634f)      // 1/sqrt(64) * log2(e)

// ---------------------------------------------------------------------------
// helpers
// ---------------------------------------------------------------------------
__device__ __forceinline__ float fexp2(float x) {
    float y;
    asm("ex2.approx.ftz.f32 %0, %1;" : "=f"(y) : "f"(x));
    return y;
}
__device__ __forceinline__ void mma_f16(float c[4],
                                        unsigned a0, unsigned a1, unsigned a2, unsigned a3,
                                        unsigned b0, unsigned b1) {
    asm volatile(
        "mma.sync.aligned.m16n8k16.row.col.f32.f16.f16.f32 "
        "{%0,%1,%2,%3}, {%4,%5,%6,%7}, {%8,%9}, {%0,%1,%2,%3};"
        : "+f"(c[0]), "+f"(c[1]), "+f"(c[2]), "+f"(c[3])
        : "r"(a0), "r"(a1), "r"(a2), "r"(a3), "r"(b0), "r"(b1));
}
__device__ __forceinline__ void ldsm4(unsigned r[4], unsigned addr) {
    asm volatile("ldmatrix.sync.aligned.m8n8.x4.shared.b16 {%0,%1,%2,%3}, [%4];"
                 : "=r"(r[0]), "=r"(r[1]), "=r"(r[2]), "=r"(r[3]) : "r"(addr));
}
__device__ __forceinline__ void ldsm4t(unsigned r[4], unsigned addr) {
    asm volatile("ldmatrix.sync.aligned.m8n8.x4.trans.shared.b16 {%0,%1,%2,%3}, [%4];"
                 : "=r"(r[0]), "=r"(r[1]), "=r"(r[2]), "=r"(r[3]) : "r"(addr));
}
__device__ __forceinline__ unsigned smem_u32(const void* p) {
    return (unsigned)__cvta_generic_to_shared(p);
}
__device__ __forceinline__ unsigned pack_h2(float lo, float hi) {
    __half2 h = __floats2half2_rn(lo, hi);
    return *reinterpret_cast<unsigned*>(&h);
}
__device__ __forceinline__ void cpa16(unsigned s, const void* g) {
    asm volatile("cp.async.cg.shared.global [%0], [%1], 16;" :: "r"(s), "l"(g) : "memory");
}
#define CP_COMMIT() asm volatile("cp.async.commit_group;" ::: "memory")
#define CP_WAIT0()  asm volatile("cp.async.wait_group 0;" ::: "memory")
#define CP_WAIT1()  asm volatile("cp.async.wait_group 1;" ::: "memory")

// ---------------------------------------------------------------------------
// fp32 -> fp16 conversion (first scaleEnd elements multiplied by scale)
// ---------------------------------------------------------------------------
__global__ void conv_f2h(const float* __restrict__ src, __half* __restrict__ dst,
                         int n, int scaleEnd, float scale)
{
    int i = (blockIdx.x * blockDim.x + threadIdx.x) * 4;
    if (i >= n) return;
    float4 v = *(const float4*)(src + i);
    if (i < scaleEnd) { v.x *= scale; v.y *= scale; v.z *= scale; v.w *= scale; }
    uint2 o;
    o.x = pack_h2(v.x, v.y);
    o.y = pack_h2(v.z, v.w);
    *(uint2*)(dst + i) = o;
}

// ---------------------------------------------------------------------------
// fp16 GEMM (NT), BK=32, 3-stage cp.async pipeline (wait_group 1),
// 8 warps, warp tile 64x32.
// Smem: half rows stride 40; 3 stages * 2 mats * 128*40*2B = 61440 B.
// ---------------------------------------------------------------------------
#define GH   40
#define GHST (128 * GH)   // halves per matrix per stage

template <bool HALF_OUT>
__global__ __launch_bounds__(256, 2) void gemm_h_db(
    const __half* __restrict__ A, const __half* __restrict__ B,
    const float* __restrict__ bias, void* __restrict__ Cv,
    int M, int Nn, int K, int scaleEnd, float bscale)
{
    extern __shared__ __half gh[];
    __half* Ah = gh;               // [3][128][40]
    __half* Bh = gh + 3 * GHST;    // [3][128][40]

    const int tid  = threadIdx.x;
    const int lane = tid & 31;
    const int warp = tid >> 5;
    const int gid  = lane >> 2;
    const int tig  = lane & 3;

    const int wm = (warp >> 2) * 64;   // 0 or 64
    const int wn = (warp & 3) * 32;    // 0,32,64,96

    const int n0 = blockIdx.x * 128;
    const int m0 = blockIdx.y * 128;

    const int lrow = tid >> 1;         // 0..127
    const int lk   = (tid & 1) * 16;   // 0 or 16 (halves)

    // ldmatrix lane offsets
    const int r16 = (lane & 7) + ((lane >> 3) & 1) * 8;
    const int ca  = (lane >> 4) * 8;
    const int cb  = ((lane >> 4) & 1) * 8;

    const unsigned aBase = smem_u32(Ah) + ((wm + r16) * GH + ca) * 2;
    const unsigned bBase = smem_u32(Bh) + ((wn + r16) * GH + cb) * 2;

    // cp.async destination addresses (this thread's slots)
    const unsigned aDst = smem_u32(Ah + lrow * GH + lk);
    const unsigned bDst = smem_u32(Bh + lrow * GH + lk);

    float acc[4][4][4];
#pragma unroll
    for (int mi = 0; mi < 4; ++mi)
#pragma unroll
        for (int ni = 0; ni < 4; ++ni)
#pragma unroll
            for (int r = 0; r < 4; ++r) acc[mi][ni][r] = 0.0f;

    const __half* Arow = A + (size_t)(m0 + lrow) * K + lk;
    const __half* Brow = B + (size_t)(n0 + lrow) * K + lk;
    const int nT = K / 32;

    // prologue: stages 0 and 1
#pragma unroll
    for (int p = 0; p < 2; ++p) {
        const unsigned soff = p * (GHST * 2);
        const __half* An = Arow + p * 32;
        const __half* Bn = Brow + p * 32;
        cpa16(aDst + soff,      An);
        cpa16(aDst + soff + 16, An + 8);
        cpa16(bDst + soff,      Bn);
        cpa16(bDst + soff + 16, Bn + 8);
        CP_COMMIT();
    }
    CP_WAIT1();          // stage 0 complete
    __syncthreads();

    for (int kt = 0; kt < nT; ++kt) {
        const int st = kt % 3;
        // issue loads for kt+2 (overlap with MMAs below); commit ALWAYS
        if (kt + 2 < nT) {
            const unsigned soff = ((kt + 2) % 3) * (GHST * 2);
            const __half* An = Arow + (kt + 2) * 32;
            const __half* Bn = Brow + (kt + 2) * 32;
            cpa16(aDst + soff,      An);
            cpa16(aDst + soff + 16, An + 8);
            cpa16(bDst + soff,      Bn);
            cpa16(bDst + soff + 16, Bn + 8);
        }
        CP_COMMIT();

        const unsigned aS = aBase + st * (GHST * 2);
        const unsigned bS = bBase + st * (GHST * 2);
#pragma unroll
        for (int ks = 0; ks < 2; ++ks) {
            const unsigned koff = ks * 32;   // 16 halves
            unsigned af[4][4], bf[2][4];
#pragma unroll
            for (int mi = 0; mi < 4; ++mi)
                ldsm4(af[mi], aS + mi * (16 * GH * 2) + koff);
#pragma unroll
            for (int ng = 0; ng < 2; ++ng)
                ldsm4(bf[ng], bS + ng * (16 * GH * 2) + koff);
#pragma unroll
            for (int mi = 0; mi < 4; ++mi)
#pragma unroll
                for (int ni = 0; ni < 4; ++ni)
                    mma_f16(acc[mi][ni], af[mi][0], af[mi][1], af[mi][2], af[mi][3],
                            bf[ni >> 1][ni & 1], bf[ni >> 1][(ni & 1) + 2]);
        }

        if (kt + 1 < nT) {
            CP_WAIT1();      // tile kt+1 landed; kt+2 may still fly
            __syncthreads();
        }
    }

    // Epilogue: bias (+optional scale) then store fp16 or fp32
#pragma unroll
    for (int ni = 0; ni < 4; ++ni) {
        const int col = n0 + wn + ni * 8 + 2 * tig;
        const float bs = (col < scaleEnd) ? bscale : 1.0f;
        const float bx = bias[col] * bs;
        const float by = bias[col + 1] * bs;
#pragma unroll
        for (int mi = 0; mi < 4; ++mi) {
            const int row = m0 + wm + mi * 16 + gid;
            if (HALF_OUT) {
                __half* C = (__half*)Cv;
                *(unsigned*)(C + (size_t)row * Nn + col) =
                    pack_h2(acc[mi][ni][0] + bx, acc[mi][ni][1] + by);
                *(unsigned*)(C + (size_t)(row + 8) * Nn + col) =
                    pack_h2(acc[mi][ni][2] + bx, acc[mi][ni][3] + by);
            } else {
                float* C = (float*)Cv;
                *(float2*)(C + (size_t)row * Nn + col) =
                    make_float2(acc[mi][ni][0] + bx, acc[mi][ni][1] + by);
                *(float2*)(C + (size_t)(row + 8) * Nn + col) =
                    make_float2(acc[mi][ni][2] + bx, acc[mi][ni][3] + by);
            }
        }
    }
}

// ---------------------------------------------------------------------------
// Flash attention: all-fp16 mma (fp32 accum), fp16 gmem I/O, 3-stage
// cp.async K/V pipeline (wait_group 1), ONE barrier per iteration.
// Smem halves: Q[128][72] | 3 x { K[64][72] | V[64][72] }
// total = 512*72*2 = 73728 B (2 CTAs/SM).
// ---------------------------------------------------------------------------
#define AH_Q  0
#define AH_K0 (128 * 72)
#define KVBUF (128 * 72)          // halves per K+V stage
#define ATT_BYTES (512 * 72 * 2)  // 73728

__global__ __launch_bounds__(256, 2) void attn_flash_f16()
{
    extern __shared__ __half ah[];
    __half* qh = ah + AH_Q;

    const int tid  = threadIdx.x;
    const int lane = tid & 31;
    const int warp = tid >> 5;
    const int gid  = lane >> 2;
    const int tig  = lane & 3;
    const int wm   = warp * 16;

    const int b  = blockIdx.y / NHEAD;
    const int h  = blockIdx.y % NHEAD;
    const int q0 = blockIdx.x * 128;

    // ldmatrix lane offsets
    const int r16 = (lane & 7) + ((lane >> 3) & 1) * 8;
    const int caQ = (lane >> 4) * 8;
    const int cbKV = ((lane >> 4) & 1) * 8;

    const unsigned qA  = smem_u32(qh) + ((wm + r16) * 72 + caQ) * 2;
    const unsigned kB0 = smem_u32(ah + AH_K0) + (r16 * 72 + cbKV) * 2;
    const unsigned vB0 = kB0 + (64 * 72) * 2;

    // ---- load Q tile (pure copy) ----
    {
        const int qrow = tid & 127;
        const int qdh  = (tid >> 7) * 32;
        const __half* src = g_qkvh + (size_t)(b * NN + q0 + qrow) * QKVW + h * HDIM + qdh;
        __half* dst = qh + qrow * 72 + qdh;
        *(uint4*)(dst)      = *(const uint4*)(src);
        *(uint4*)(dst + 8)  = *(const uint4*)(src + 8);
        *(uint4*)(dst + 16) = *(const uint4*)(src + 16);
        *(uint4*)(dst + 24) = *(const uint4*)(src + 24);
    }

    // K/V loader: kr = row, sel 0,1 = K d-halves; 2,3 = V d-halves
    const int kr   = tid & 63;
    const int sel  = tid >> 6;
    const int kdh  = (sel & 1) * 32;
    const size_t kvoff = (size_t)h * HDIM + kdh + ((sel >> 1) ? 2 * EMBED : EMBED);
    const unsigned kvDst0 = smem_u32(ah + AH_K0 + ((sel >> 1) ? 64 * 72 : 0) + kr * 72 + kdh);
    const __half* kvSrc = g_qkvh + (size_t)(b * NN + kr) * QKVW + kvoff;

    const int NT = NN / 64;
    // prologue: tiles 0 and 1 into stages 0 and 1
#pragma unroll
    for (int p = 0; p < 2; ++p) {
        const unsigned d = kvDst0 + (p * KVBUF) * 2;
        const __half* s2 = kvSrc + (size_t)p * 64 * QKVW;
#pragma unroll
        for (int u = 0; u < 4; ++u)
            cpa16(d + u * 16, s2 + u * 8);
        CP_COMMIT();
    }
    CP_WAIT1();          // tile 0 complete
    __syncthreads();

    float m0r = -1.0e30f, m1r = -1.0e30f;
    float l0 = 0.0f, l1 = 0.0f;
    float O[8][4];
#pragma unroll
    for (int ni = 0; ni < 8; ++ni)
#pragma unroll
        for (int r = 0; r < 4; ++r) O[ni][r] = 0.0f;

    for (int kt = 0; kt < NT; ++kt) {
        const int buf = kt % 3;
        // issue tile kt+2 into stage (kt+2)%3; commit ALWAYS
        if (kt + 2 < NT) {
            const unsigned d = kvDst0 + (((kt + 2) % 3) * KVBUF) * 2;
            const __half* s2 = kvSrc + (size_t)(kt + 2) * 64 * QKVW;
#pragma unroll
            for (int u = 0; u < 4; ++u)
                cpa16(d + u * 16, s2 + u * 8);
        }
        CP_COMMIT();

        const unsigned kB = kB0 + buf * (KVBUF * 2);
        const unsigned vB = vB0 + buf * (KVBUF * 2);

        // ---- S = Qhat @ K^T (fp16 mma) ----
        float s[8][4];
#pragma unroll
        for (int ni = 0; ni < 8; ++ni)
#pragma unroll
            for (int r = 0; r < 4; ++r) s[ni][r] = 0.0f;
#pragma unroll
        for (int ks = 0; ks < 4; ++ks) {          // d in 16-chunks
            unsigned aq[4];
            ldsm4(aq, qA + ks * 32);
#pragma unroll
            for (int j = 0; j < 4; ++j) {         // key 16-groups
                unsigned bk[4];
                ldsm4(bk, kB + j * (16 * 72 * 2) + ks * 32);
                mma_f16(s[2 * j],     aq[0], aq[1], aq[2], aq[3], bk[0], bk[2]);
                mma_f16(s[2 * j + 1], aq[0], aq[1], aq[2], aq[3], bk[1], bk[3]);
            }
        }

        // ---- online softmax (log2 domain) ----
        float rm0 = -1.0e30f, rm1 = -1.0e30f;
#pragma unroll
        for (int ni = 0; ni < 8; ++ni) {
            rm0 = fmaxf(rm0, fmaxf(s[ni][0], s[ni][1]));
            rm1 = fmaxf(rm1, fmaxf(s[ni][2], s[ni][3]));
        }
        rm0 = fmaxf(rm0, __shfl_xor_sync(0xffffffffu, rm0, 1));
        rm0 = fmaxf(rm0, __shfl_xor_sync(0xffffffffu, rm0, 2));
        rm1 = fmaxf(rm1, __shfl_xor_sync(0xffffffffu, rm1, 1));
        rm1 = fmaxf(rm1, __shfl_xor_sync(0xffffffffu, rm1, 2));

        const float mn0 = fmaxf(m0r, rm0);
        const float mn1 = fmaxf(m1r, rm1);
        const float al0 = fexp2(m0r - mn0);
        const float al1 = fexp2(m1r - mn1);
        m0r = mn0; m1r = mn1;

        float ps0 = 0.0f, ps1 = 0.0f;
#pragma unroll
        for (int ni = 0; ni < 8; ++ni) {
            s[ni][0] = fexp2(s[ni][0] - mn0);
            s[ni][1] = fexp2(s[ni][1] - mn0);
            s[ni][2] = fexp2(s[ni][2] - mn1);
            s[ni][3] = fexp2(s[ni][3] - mn1);
            ps0 += s[ni][0] + s[ni][1];
            ps1 += s[ni][2] + s[ni][3];
        }
        ps0 += __shfl_xor_sync(0xffffffffu, ps0, 1);
        ps0 += __shfl_xor_sync(0xffffffffu, ps0, 2);
        ps1 += __shfl_xor_sync(0xffffffffu, ps1, 1);
        ps1 += __shfl_xor_sync(0xffffffffu, ps1, 2);
        l0 = l0 * al0 + ps0;
        l1 = l1 * al1 + ps1;

#pragma unroll
        for (int ni = 0; ni < 8; ++ni) {
            O[ni][0] *= al0; O[ni][1] *= al0;
            O[ni][2] *= al1; O[ni][3] *= al1;
        }

        // ---- O += P @ V : P in registers, V via ldmatrix.trans ----
#pragma unroll
        for (int j = 0; j < 4; ++j) {             // key 16-groups (k dim)
            const unsigned a0 = pack_h2(s[2 * j][0],     s[2 * j][1]);
            const unsigned a1 = pack_h2(s[2 * j][2],     s[2 * j][3]);
            const unsigned a2 = pack_h2(s[2 * j + 1][0], s[2 * j + 1][1]);
            const unsigned a3 = pack_h2(s[2 * j + 1][2], s[2 * j + 1][3]);
#pragma unroll
            for (int p = 0; p < 4; ++p) {         // d 16-groups (n dim)
                unsigned bv[4];
                ldsm4t(bv, vB + j * (16 * 72 * 2) + p * 32);
                mma_f16(O[2 * p],     a0, a1, a2, a3, bv[0], bv[1]);
                mma_f16(O[2 * p + 1], a0, a1, a2, a3, bv[2], bv[3]);
            }
        }

        if (kt + 1 < NT) {
            CP_WAIT1();      // tile kt+1 landed; kt+2 may still fly
            __syncthreads();
        }
    }

    // ---- normalize and write ctx (fp16) ----
    const float inv0 = 1.0f / l0;
    const float inv1 = 1.0f / l1;
    __half* dst0 = g_ctxh + (size_t)(b * NN + q0 + wm + gid) * EMBED + h * HDIM;
    __half* dst1 = g_ctxh + (size_t)(b * NN + q0 + wm + gid + 8) * EMBED + h * HDIM;
#pragma unroll
    for (int ni = 0; ni < 8; ++ni) {
        const int col = ni * 8 + 2 * tig;
        *(unsigned*)(dst0 + col) = pack_h2(O[ni][0] * inv0, O[ni][1] * inv0);
        *(unsigned*)(dst1 + col) = pack_h2(O[ni][2] * inv1, O[ni][3] * inv1);
    }
}

// ---------------------------------------------------------------------------
extern "C" void kernel_launch(void* const* d_in, const int* in_sizes, int n_in,
                              void* d_out, int out_size)
{
    (void)in_sizes; (void)n_in; (void)out_size;
    const float* x     = (const float*)d_in[0];
    const float* w_qkv = (const float*)d_in[1];
    const float* b_qkv = (const float*)d_in[2];
    const float* w_out = (const float*)d_in[3];
    const float* b_out = (const float*)d_in[4];
    float* out = (float*)d_out;

    __half *xh, *wqkvh, *wouth, *qkvh, *ctxh;
    cudaGetSymbolAddress((void**)&xh,    g_xh);
    cudaGetSymbolAddress((void**)&wqkvh, g_wqkvh);
    cudaGetSymbolAddress((void**)&wouth, g_wouth);
    cudaGetSymbolAddress((void**)&qkvh,  g_qkvh);
    cudaGetSymbolAddress((void**)&ctxh,  g_ctxh);

    const int gemm_smem = 6 * GHST * 2;   // 61440
    const int attn_smem = ATT_BYTES;      // 73728

    static int attrs_set = 0;
    if (!attrs_set) {
        cudaFuncSetAttribute(gemm_h_db<true>,
                             cudaFuncAttributeMaxDynamicSharedMemorySize, gemm_smem);
        cudaFuncSetAttribute(gemm_h_db<false>,
                             cudaFuncAttributeMaxDynamicSharedMemorySize, gemm_smem);
        cudaFuncSetAttribute(attn_flash_f16,
                             cudaFuncAttributeMaxDynamicSharedMemorySize, attn_smem);
        attrs_set = 1;
    }

    // 0) fp32 -> fp16 conversions (Q rows of w_qkv pre-scaled by QSCALE)
    {
        const int n1 = MTOT * EMBED;
        conv_f2h<<<n1 / 4 / 256, 256>>>(x, xh, n1, 0, 1.0f);
        const int n2 = QKVW * EMBED;
        conv_f2h<<<n2 / 4 / 256, 256>>>(w_qkv, wqkvh, n2, EMBED * EMBED, QSCALE);
        const int n3 = EMBED * EMBED;
        conv_f2h<<<n3 / 4 / 256, 256>>>(w_out, wouth, n3, 0, 1.0f);
    }

    // 1) QKV projection (half in, half out; Q bias scaled in epilogue)
    {
        dim3 grid(QKVW / 128, MTOT / 128);
        gemm_h_db<true><<<grid, 256, gemm_smem>>>(xh, wqkvh, b_qkv, qkvh,
                                                  MTOT, QKVW, EMBED, EMBED, QSCALE);
    }

    // 2) Flash attention (all fp16 I/O, 3-stage cp.async K/V)
    {
        dim3 grid(NN / 128, BB * NHEAD);
        attn_flash_f16<<<grid, 256, attn_smem>>>();
    }

    // 3) Output projection (half in, fp32 out + bias)
    {
        dim3 grid(EMBED / 128, MTOT / 128);
        gemm_h_db<false><<<grid, 256, gemm_smem>>>(ctxh, wouth, b_out, out,
                                                   MTOT, EMBED, EMBED, 0, 1.0f);
    }
}